// round 17
// baseline (speedup 1.0000x reference)
#include <cuda_runtime.h>

#define NB 128
#define NT 1024
#define ND 3
#define NH 512
#define NC 3
#define NSLICE 16      // h-slices per batch group = CTAs per group = cluster
#define HS 32          // h per slice
#define NGRP 16        // batch groups (8 rows); each CTA serves 2 groups
#define BGr 8          // batch rows per group
#define THREADS 512
#define RSTRIDE 516    // rW row stride in words (pad -> conflict-free A loads)
#define PSTRIDE 34     // psum row stride in words
#define PSUMW (4 * 2 * 16 * PSTRIDE)   // words per psum buffer
#define NFLAG (2 * NSLICE * BGr)       // smem flags: [grp2][slice][row]

typedef unsigned int u32;

// fallback-path flags (used only when cluster-16 unavailable): per-(group,
// slice,row,t), parity-based, zero-initialized, flips once per launch.
__device__ int g_flag[NGRP][NSLICE][BGr][NT];

static __device__ __forceinline__ void wait_flag(const int* pf, int stale) {
    int v;
    do {
        asm volatile("ld.acquire.gpu.global.s32 %0, [%1];"
                     : "=r"(v) : "l"(pf) : "memory");
    } while (v == stale);
}
static __device__ __forceinline__ u32 smem_addr32(const void* p) {
    u32 a;
    asm("{ .reg .u64 t; cvta.to.shared.u64 t, %1; cvt.u32.u64 %0, t; }"
        : "=r"(a) : "l"(p));
    return a;
}
static __device__ __forceinline__ u32 mapa_rank(u32 laddr, int rank) {
    u32 r;
    asm("mapa.shared::cluster.u32 %0, %1, %2;" : "=r"(r) : "r"(laddr), "r"(rank));
    return r;
}
static __device__ __forceinline__ void st_rel_cluster(u32 raddr, int v) {
    asm volatile("st.release.cluster.shared::cluster.s32 [%0], %1;"
                 :: "r"(raddr), "r"(v) : "memory");
}
static __device__ __forceinline__ int ld_acq_smem(u32 laddr) {
    int v;
    asm volatile("ld.acquire.cluster.shared::cta.s32 %0, [%1];"
                 : "=r"(v) : "r"(laddr) : "memory");
    return v;
}
static __device__ __forceinline__ u32 to_tf32(float f) {
    u32 o; asm("cvt.rna.tf32.f32 %0, %1;" : "=r"(o) : "f"(f)); return o;
}
static __device__ __forceinline__ void mma_tf32(
    float& c0, float& c1, float& c2, float& c3,
    u32 a0, u32 a1, u32 a2, u32 a3, u32 b0, u32 b1)
{
    asm volatile(
        "mma.sync.aligned.m16n8k8.row.col.f32.tf32.tf32.f32 "
        "{%0,%1,%2,%3}, {%4,%5,%6,%7}, {%8,%9}, {%0,%1,%2,%3};"
        : "+f"(c0), "+f"(c1), "+f"(c2), "+f"(c3)
        : "r"(a0), "r"(a1), "r"(a2), "r"(a3), "r"(b0), "r"(b1));
}

extern __shared__ float smem_f[];

// Grid 128 = 8 pairs x 16 slices; one cluster per pair when dsm=1.
// Skewed single-pass scheme: mma rows 0-7 = gA step t, rows 8-15 = gB step t-1.
// Warp w = hq*4+kq. Stage: tile rows hq*4..+4 of k-strip kq (raw fp32; tf32
// HMMA reads top bits). Poll: lanes 0-15, one (slice,row) each — own-smem
// step counters (dsm) or global parity flags (fallback). Reduce: warp w owns
// mma row w; publishes via 16 DSMEM release-stores (dsm) or 1 global release.
__global__ void __launch_bounds__(THREADS, 1)
flipflop_main(const float* __restrict__ inputs,
              const float* __restrict__ Wv,
              const float* __restrict__ Pv,
              const float* __restrict__ bv,
              const float* __restrict__ Wz,
              const float* __restrict__ Pz,
              const float* __restrict__ bz,
              const float* __restrict__ fcW,
              const float* __restrict__ fcb,
              float* __restrict__ out,
              float* __restrict__ hidden,
              const int dsm)
{
    u32*   rW  = (u32*)smem_f;                // [16][RSTRIDE] fp32 bits, 33 KB
    float* ps  = smem_f + 16 * RSTRIDE;       // 2 x [4kq][2][16rows][PSTRIDE]
    int*   sfl = (int*)(ps + 2 * PSUMW);      // [2][NSLICE][BGr] step counters

    const int tid   = threadIdx.x;
    const int pair  = blockIdx.x >> 4;
    const int slice = blockIdx.x & 15;        // == cluster rank when dsm
    const int gA    = pair * 2, gB = gA + 1;
    const int gbA   = gA * BGr, gbB = gB * BGr;
    const int w     = tid >> 5;
    const int lane  = tid & 31;
    const int hq    = w >> 2;
    const int kq    = w & 3;
    const int g     = lane >> 2;
    const int t4    = lane & 3;
    const int hh    = lane;
    const int hg    = slice * HS + hh;

    // ---- B fragments (weights) in registers, tf32 RNA, 64 regs ----
    u32 bz0[16], bz1[16], bv0[16], bv1[16];
    {
        const int hB = slice * HS + hq * 8 + g;
        const float* zrow = Wz + (size_t)hB * NH + kq * 128 + t4;
        const float* vrow = Wv + (size_t)hB * NH + kq * 128 + t4;
        #pragma unroll
        for (int kb = 0; kb < 16; ++kb) {
            bz0[kb] = to_tf32(zrow[kb*8]);
            bz1[kb] = to_tf32(zrow[kb*8 + 4]);
            bv0[kb] = to_tf32(vrow[kb*8]);
            bv1[kb] = to_tf32(vrow[kb*8 + 4]);
        }
    }

    // fallback parity probes (harmless reads in dsm mode)
    int parA, parB;
    asm volatile("ld.relaxed.gpu.global.s32 %0, [%1];"
                 : "=r"(parA) : "l"(&g_flag[gA][slice][0][NT-1]));
    asm volatile("ld.relaxed.gpu.global.s32 %0, [%1];"
                 : "=r"(parB) : "l"(&g_flag[gB][slice][0][NT-1]));
    const int readyA = parA ^ 1, readyB = parB ^ 1;

    // ---- reduce-role constants ----
    const float pz0 = Pz[hg*3+0], pz1 = Pz[hg*3+1], pz2 = Pz[hg*3+2];
    float pm0 = 0.f, pm1 = 0.f, pm2 = 0.f;        // P_m: bottom half zeroed
    if (hg < NH/2) { pm0 = Pv[hg*3+0]; pm1 = Pv[hg*3+1]; pm2 = Pv[hg*3+2]; }
    const float bzr = bz[hg];
    const float bvr = bv[hg];
    const int   rrow  = w & 7;
    const int   myrow = (w < 8) ? (gbA + rrow) : (gbB + rrow);
    const float* xrow = inputs + (size_t)myrow * NT * ND;
    float*       hout = hidden + ((size_t)myrow * NT) * NH + hg;
    int* myflag = (w < 8) ? &g_flag[gA][slice][rrow][0]
                          : &g_flag[gB][slice][rrow][0];
    const int myready = (w < 8) ? readyA : readyB;
    // dsm: byte offset of this warp's flag slot (same in every CTA's smem)
    const int  myslot = ((w < 8) ? 0 : 1) * NSLICE * BGr + slice * BGr + rrow;
    const u32  myslot_l = smem_addr32(&sfl[myslot]);

    // ---- stage-role: warp stages tile rows [hq*4, hq*4+4) of k-strip kq ----
    const bool stA    = (hq < 2);                 // tile rows 0-7 <- group A
    const int  srow   = hq * 4 + (lane >> 3);     // tile row 0..15
    const int  sch    = (lane & 7) * 4;           // word chunk within window
    const int  sgrow  = stA ? (gbA + (srow & 7)) : (gbB + (srow & 7));
    const float* sg   = hidden + ((size_t)sgrow * NT) * NH + kq * 128 + sch;
    u32*        sd    = rW + srow * RSTRIDE + kq * 128 + sch;

    // ---- poll-role: lane l<16 polls (slice kq*4 + (l&3), group-row ...) ----
    const int  ps_s   = lane & 3;                 // producer slice within quad
    const int  ps_r   = ((hq & 1) * 4 + (lane >> 2)) & 7;   // group row
    const int* pollp  = stA ? &g_flag[gA][kq*4 + ps_s][ps_r][0]
                            : &g_flag[gB][kq*4 + ps_s][ps_r][0];
    const int  pollpar = stA ? parA : parB;
    const int  pslot  = (stA ? 0 : 1) * NSLICE * BGr + (kq*4 + ps_s) * BGr + ps_r;
    const u32  pslot_l = smem_addr32(&sfl[pslot]);

    // ---- A-frag / psum indices ----
    const int ab0 = g * RSTRIDE + t4;
    const int ab1 = (g + 8) * RSTRIDE + t4;
    const int koff0 = kq * 128;
    const int psz_i = ((kq * 2 + 0) * 16 + g) * PSTRIDE + hq * 8 + t4 * 2;
    const int psv_i = ((kq * 2 + 1) * 16 + g) * PSTRIDE + hq * 8 + t4 * 2;

    // zero rW (r0 = 0) and init smem flags to -1
    for (int i = tid; i < 16 * RSTRIDE; i += THREADS) rW[i] = 0u;
    for (int i = tid; i < NFLAG; i += THREADS) sfl[i] = -1;
    __syncthreads();
    if (dsm) {   // flags must be visible cluster-wide before any remote store
        asm volatile("barrier.cluster.arrive.aligned;" ::: "memory");
        asm volatile("barrier.cluster.wait.aligned;" ::: "memory");
    }

    float r_prev = 0.f;          // w<8: r_A(t-1)[row]; w>=8: r_B(t-2)[row]

    for (int t = 0; t <= NT; ++t) {
        // prefetch this warp's x (A: step t; B: step t-1)
        float x0 = 0.f, x1 = 0.f, x2 = 0.f;
        {
            const int xs = (w < 8) ? t : (t - 1);
            if (xs >= 0 && xs < NT) {
                x0 = xrow[xs*3+0]; x1 = xrow[xs*3+1]; x2 = xrow[xs*3+2];
            }
        }

        const bool do_stage = stA ? (t >= 1 && t < NT) : (t >= 2);
        const int  tsrc     = stA ? (t - 1) : (t - 2);

        // ---- poll: 16 lanes in parallel, one (slice,row) each ----
        if (do_stage && lane < 16) {
            if (dsm) { while (ld_acq_smem(pslot_l) < tsrc) {} }
            else     { wait_flag(pollp + tsrc, pollpar); }
        }
        __syncwarp();

        // ---- stage: raw fp32 copy (tf32 HMMA ignores low mantissa) ----
        if (do_stage) {
            const float* s = sg + (size_t)tsrc * NH;
            #pragma unroll
            for (int j = 0; j < 4; ++j)                   // windows of 32 k
                *(uint4*)(sd + j * 32) = *(const uint4*)(s + j * 32);
        }
        asm volatile("bar.sync %0, 128;" :: "r"(1 + kq) : "memory");

        // ---- single mma pass: rows 0-7 = A(t), rows 8-15 = B(t-1) ----
        float* pb = ps + (t & 1) * PSUMW;
        if (t >= 1) {
            float cz0=0.f,cz1=0.f,cz2=0.f,cz3=0.f, cv0=0.f,cv1=0.f,cv2=0.f,cv3=0.f;
            #pragma unroll
            for (int kb = 0; kb < 16; ++kb) {
                const int ko = koff0 + kb * 8;
                u32 a0 = rW[ab0 + ko], a1 = rW[ab1 + ko];
                u32 a2 = rW[ab0 + ko + 4], a3 = rW[ab1 + ko + 4];
                mma_tf32(cz0,cz1,cz2,cz3, a0,a1,a2,a3, bz0[kb],bz1[kb]);
                mma_tf32(cv0,cv1,cv2,cv3, a0,a1,a2,a3, bv0[kb],bv1[kb]);
            }
            *(float2*)(pb + psz_i)               = make_float2(cz0, cz1);
            *(float2*)(pb + psz_i + 8 * PSTRIDE) = make_float2(cz2, cz3);
            *(float2*)(pb + psv_i)               = make_float2(cv0, cv1);
            *(float2*)(pb + psv_i + 8 * PSTRIDE) = make_float2(cv2, cv3);
        }
        __syncthreads();                          // psum complete (only CTA sync)

        // ---- reduce + gates + publish: warp w owns mma row w ----
        {
            const int xs   = (w < 8) ? t : (t - 1);      // step this warp emits
            const bool run = (xs >= 0) && (xs < NT);
            const bool hasp = (w < 8) ? (t >= 1) : (t >= 2);
            if (run) {
                float sz = 0.f, sv = 0.f;
                if (hasp) {
                    #pragma unroll
                    for (int q = 0; q < 4; ++q) {
                        sz += pb[((q*2 + 0) * 16 + w) * PSTRIDE + hh];
                        sv += pb[((q*2 + 1) * 16 + w) * PSTRIDE + hh];
                    }
                }
                const float az = sz + x0*pz0 + x1*pz1 + x2*pz2 + bzr;
                const float av = sv + x0*pm0 + x1*pm1 + x2*pm2 + bvr;
                const float z  = 1.f / (1.f + __expf(-az));
                const float c  = 1.f / (1.f + __expf(-av));
                const float rn = fmaf(z, c - r_prev, r_prev);
                r_prev = rn;
                hout[(size_t)xs * NH] = rn;
                __syncwarp();                     // order lane STGs before release
                if (dsm) {
                    if (lane < NSLICE)            // push step counter to all CTAs
                        st_rel_cluster(mapa_rank(myslot_l, lane), xs);
                } else if (hh == 0) {
                    asm volatile("st.release.gpu.global.s32 [%0], %1;"
                                 :: "l"(myflag + xs), "r"(myready) : "memory");
                }
            }
        }
    }

    // before fc: wait for every (group,slice,row) stream to reach NT-1
    if (dsm) {
        if (tid < NFLAG) {
            const u32 a = smem_addr32(&sfl[tid]);
            while (ld_acq_smem(a) < NT - 1) {}
        }
    } else {
        if (lane < 8)       wait_flag(&g_flag[gA][w][lane][NT-1], parA);
        else if (lane < 16) wait_flag(&g_flag[gB][w][lane-8][NT-1], parB);
    }
    __syncthreads();

    // ================= fc epilogue =================
    float* fw = smem_f;                           // reuse smem
    for (int i = tid; i < NC * NH; i += THREADS) fw[i] = fcW[i];
    const float fb0 = fcb[0], fb1 = fcb[1], fb2 = fcb[2];
    __syncthreads();

    float4 fw0[4], fw1[4], fw2[4];
    #pragma unroll
    for (int j = 0; j < 4; ++j) {
        const int i = hh + j * 32;
        fw0[j] = ((const float4*)(fw + 0 * NH))[i];
        fw1[j] = ((const float4*)(fw + 1 * NH))[i];
        fw2[j] = ((const float4*)(fw + 2 * NH))[i];
    }

    const int row = myrow;
    const int t0  = slice * (NT / NSLICE);
    const float* hp = hidden + ((size_t)row * NT + t0) * NH;
    float*       op = out    + ((size_t)row * NT + t0) * NC;

    for (int it = 0; it < NT / NSLICE; ++it) {
        const float4* h4 = (const float4*)(hp + (size_t)it * NH);
        float a0 = 0.f, a1 = 0.f, a2 = 0.f;
        #pragma unroll
        for (int j = 0; j < 4; ++j) {
            float4 h = h4[hh + j * 32];
            a0 += h.x*fw0[j].x + h.y*fw0[j].y + h.z*fw0[j].z + h.w*fw0[j].w;
            a1 += h.x*fw1[j].x + h.y*fw1[j].y + h.z*fw1[j].z + h.w*fw1[j].w;
            a2 += h.x*fw2[j].x + h.y*fw2[j].y + h.z*fw2[j].z + h.w*fw2[j].w;
        }
        #pragma unroll
        for (int o = 16; o; o >>= 1) {
            a0 += __shfl_down_sync(0xffffffffu, a0, o);
            a1 += __shfl_down_sync(0xffffffffu, a1, o);
            a2 += __shfl_down_sync(0xffffffffu, a2, o);
        }
        if (hh == 0) {
            op[it*3+0] = a0 + fb0;
            op[it*3+1] = a1 + fb1;
            op[it*3+2] = a2 + fb2;
        }
    }

    // exit safety: no CTA may leave while cluster mates can still store here
    if (dsm) {
        asm volatile("barrier.cluster.arrive.aligned;" ::: "memory");
        asm volatile("barrier.cluster.wait.aligned;" ::: "memory");
    }
}

extern "C" void kernel_launch(void* const* d_in, const int* in_sizes, int n_in,
                              void* d_out, int out_size)
{
    const float* inputs = (const float*)d_in[0];
    const float* Wv     = (const float*)d_in[1];
    const float* Pv     = (const float*)d_in[2];
    const float* b_v    = (const float*)d_in[3];
    const float* Wz     = (const float*)d_in[4];
    const float* Pz     = (const float*)d_in[5];
    const float* b_z    = (const float*)d_in[6];
    const float* fcW    = (const float*)d_in[7];
    const float* fcb    = (const float*)d_in[8];

    // outputs concatenated in reference return order: out (B,T,C) then hidden (B,T,H)
    float* out    = (float*)d_out;
    float* hidden = out + (size_t)NB * NT * NC;

    const int smem_bytes = (16 * RSTRIDE + 2 * PSUMW + NFLAG) * 4;
    cudaFuncSetAttribute(flipflop_main,
                         cudaFuncAttributeMaxDynamicSharedMemorySize, smem_bytes);
    cudaFuncSetAttribute(flipflop_main,
                         cudaFuncAttributeNonPortableClusterSizeAllowed, 1);

    // capability probe (pure query, deterministic, capture-safe)
    int maxc = 0;
    {
        cudaLaunchConfig_t qcfg = {};
        qcfg.gridDim  = dim3(NB, 1, 1);
        qcfg.blockDim = dim3(THREADS, 1, 1);
        qcfg.dynamicSmemBytes = smem_bytes;
        if (cudaOccupancyMaxPotentialClusterSize(&maxc, (const void*)flipflop_main,
                                                 &qcfg) != cudaSuccess)
            maxc = 0;
    }

    if (maxc >= NSLICE) {
        cudaLaunchConfig_t cfg = {};
        cfg.gridDim  = dim3(NB, 1, 1);
        cfg.blockDim = dim3(THREADS, 1, 1);
        cfg.dynamicSmemBytes = smem_bytes;
        cudaLaunchAttribute attrs[1];
        attrs[0].id = cudaLaunchAttributeClusterDimension;
        attrs[0].val.clusterDim.x = NSLICE;
        attrs[0].val.clusterDim.y = 1;
        attrs[0].val.clusterDim.z = 1;
        cfg.attrs = attrs;
        cfg.numAttrs = 1;
        cudaLaunchKernelEx(&cfg, flipflop_main,
                           inputs, Wv, Pv, b_v, Wz, Pz, b_z, fcW, fcb,
                           out, hidden, 1);
    } else {
        flipflop_main<<<NB, THREADS, smem_bytes>>>(
            inputs, Wv, Pv, b_v, Wz, Pz, b_z, fcW, fcb, out, hidden, 0);
    }
}